// round 5
// baseline (speedup 1.0000x reference)
#include <cuda_runtime.h>
#include <cuda_bf16.h>
#include <math.h>

#define NN 50000          // nodes
#define E2 400000         // directed edges
#define FH 96             // FD*HID
#define NBLK 196          // ceil(NN/256)

typedef unsigned long long ull;

// ---------------- device scratch ----------------
__device__ float g_xc[NN * FH];
__device__ float g_y[NN * FH];
__device__ float4 g_n4[NN];            // {PA, PB, WA, WB}
__device__ float g_deg[NN], g_dinv[NN];
__device__ int   g_cnt[NN];
__device__ int   g_off[NN + 1];
__device__ int   g_cur[NN];
__device__ int   g_bsum[NBLK];
__device__ int   g_bbase[256];
__device__ int   g_colc[E2];
__device__ float4 g_e4[E2];            // {w2, Tc, Ts, bitcast(col)}
__device__ float g_Wl[2][9];
__device__ float g_WrT[2][1024];       // transposed: [h*32 + c]
__device__ float g_coeff[2][3];

// ---------------- helpers ----------------
__device__ __forceinline__ float eluf(float v) { return v > 0.f ? v : expm1f(v); }
__device__ __forceinline__ float fsigm(float v) { return 1.f / (1.f + __expf(-v)); }
__device__ __forceinline__ float ftanh(float v) { return 1.f - 2.f / (__expf(2.f * v) + 1.f); }
__device__ __forceinline__ float wsum(float v) {
#pragma unroll
    for (int o = 16; o > 0; o >>= 1) v += __shfl_xor_sync(0xffffffffu, v, o);
    return v;
}
__device__ __forceinline__ void ffma2(ull& d, ull a, ull b) {
    asm("fma.rn.f32x2 %0, %1, %2, %0;" : "+l"(d) : "l"(a), "l"(b));
}
__device__ __forceinline__ ull pk2(float v) {
    ull r; asm("mov.b64 %0, {%1, %1};" : "=l"(r) : "f"(v)); return r;
}
__device__ __forceinline__ void upk2(float& lo, float& hi, ull v) {
    asm("mov.b64 {%0, %1}, %2;" : "=f"(lo), "=f"(hi) : "l"(v));
}

// ---------------- CSR build ----------------
__global__ void k_zero_cnt() {
    int i = blockIdx.x * blockDim.x + threadIdx.x;
    if (i < NN) g_cnt[i] = 0;
}
__global__ void k_count(const int* __restrict__ ei) {
    int e = blockIdx.x * blockDim.x + threadIdx.x;
    if (e < E2) atomicAdd(&g_cnt[ei[e]], 1);
}
__global__ void k_scanA() {
    __shared__ int s[256];
    int b = blockIdx.x, t = threadIdx.x, i = b * 256 + t;
    int v = (i < NN) ? g_cnt[i] : 0;
    s[t] = v;
    __syncthreads();
#pragma unroll
    for (int d = 1; d < 256; d <<= 1) {
        int x = (t >= d) ? s[t - d] : 0;
        __syncthreads();
        s[t] += x;
        __syncthreads();
    }
    if (i < NN) g_off[i] = s[t] - v;     // exclusive within block
    if (t == 255) g_bsum[b] = s[255];
}

// scanB fused with spectral norm: block 0 = scan of block sums, blocks 1,2 = specnorm layer 0/1
__global__ void k_scanB_spec(const float* __restrict__ W_left,
                             const float* __restrict__ W_right,
                             const float* __restrict__ eps) {
    if (blockIdx.x == 0) {
        __shared__ int s[256];
        int t = threadIdx.x;
        int v = (t < NBLK) ? g_bsum[t] : 0;
        s[t] = v;
        __syncthreads();
#pragma unroll
        for (int d = 1; d < 256; d <<= 1) {
            int x = (t >= d) ? s[t - d] : 0;
            __syncthreads();
            s[t] += x;
            __syncthreads();
        }
        g_bbase[t] = s[t] - v;
        if (t == 255) g_off[NN] = s[255];
        return;
    }
    // ---- spectral norm part (one warp active per block) ----
    int layer = blockIdx.x - 1;
    int lane = threadIdx.x;
    if (lane >= 32) return;
    __shared__ float ws[32 * 33];
    for (int i = lane; i < 1024; i += 32) {
        int r = i >> 5, c = i & 31;
        ws[r * 33 + c] = W_right[layer * 1024 + i];
    }
    __syncwarp();
    float u = 1.f / sqrtf(32.f);
    for (int it = 0; it < 20; it++) {
        // v = W^T u (skip v normalization: direction of u unchanged)
        float v = 0.f;
#pragma unroll 8
        for (int i = 0; i < 32; i++) v += ws[i * 33 + lane] * __shfl_sync(0xffffffffu, u, i);
        float un = 0.f;
#pragma unroll 8
        for (int j = 0; j < 32; j++) un += ws[lane * 33 + j] * __shfl_sync(0xffffffffu, v, j);
        float nu = sqrtf(wsum(un * un));
        u = un / (nu + 1e-12f);
    }
    float v = 0.f;
    for (int i = 0; i < 32; i++) v += ws[i * 33 + lane] * __shfl_sync(0xffffffffu, u, i);
    float nv = sqrtf(wsum(v * v));
    v = v / (nv + 1e-12f);
    float wv = 0.f;
    for (int j = 0; j < 32; j++) wv += ws[lane * 33 + j] * __shfl_sync(0xffffffffu, v, j);
    float sigma = wsum(u * wv);
    float inv = 1.f / sigma;
    for (int i = lane; i < 1024; i += 32) {
        int c = i >> 5, h = i & 31;
        g_WrT[layer][h * 32 + c] = W_right[layer * 1024 + i] * inv;
    }

    if (lane == 0) {
        float W[9];
        for (int i = 0; i < 9; i++) W[i] = W_left[layer * 9 + i];
        float uu[3] = {0.5773502691896258f, 0.5773502691896258f, 0.5773502691896258f};
        float vv[3];
        for (int it = 0; it < 20; it++) {
            vv[0] = vv[1] = vv[2] = 0.f;
            for (int i = 0; i < 3; i++)
                for (int j = 0; j < 3; j++) vv[j] += W[i * 3 + j] * uu[i];
            float n2 = sqrtf(vv[0] * vv[0] + vv[1] * vv[1] + vv[2] * vv[2]) + 1e-12f;
            for (int j = 0; j < 3; j++) vv[j] /= n2;
            float u2[3] = {0.f, 0.f, 0.f};
            for (int i = 0; i < 3; i++)
                for (int j = 0; j < 3; j++) u2[i] += W[i * 3 + j] * vv[j];
            float n3 = sqrtf(u2[0] * u2[0] + u2[1] * u2[1] + u2[2] * u2[2]) + 1e-12f;
            for (int i = 0; i < 3; i++) uu[i] = u2[i] / n3;
        }
        vv[0] = vv[1] = vv[2] = 0.f;
        for (int i = 0; i < 3; i++)
            for (int j = 0; j < 3; j++) vv[j] += W[i * 3 + j] * uu[i];
        float n2 = sqrtf(vv[0] * vv[0] + vv[1] * vv[1] + vv[2] * vv[2]) + 1e-12f;
        for (int j = 0; j < 3; j++) vv[j] /= n2;
        float sig = 0.f;
        for (int i = 0; i < 3; i++) {
            float t = 0.f;
            for (int j = 0; j < 3; j++) t += W[i * 3 + j] * vv[j];
            sig += uu[i] * t;
        }
        float is = 1.f / sig;
        for (int i = 0; i < 9; i++) g_Wl[layer][i] = W[i] * is;
        for (int f = 0; f < 3; f++) g_coeff[layer][f] = 1.f + tanhf(eps[layer * 3 + f]);
    }
}

__global__ void k_scanC() {
    int i = blockIdx.x * blockDim.x + threadIdx.x;
    if (i < NN) {
        int o = g_off[i] + g_bbase[i >> 8];
        g_off[i] = o;
        g_cur[i] = o;
    }
}
__global__ void k_scatter(const int* __restrict__ ei) {
    int e = blockIdx.x * blockDim.x + threadIdx.x;
    if (e < E2) {
        int r = ei[e];
        int p = atomicAdd(&g_cur[r], 1);
        g_colc[p] = ei[E2 + e];
    }
}

// ---------------- lin1: xc = elu(x @ W1^T + b1), FFMA2 register tiling ----------------
#define XS_LD 134
#define WS_LD 98
__global__ void __launch_bounds__(256) k_lin1(const float* __restrict__ x,
                                              const float* __restrict__ W1,
                                              const float* __restrict__ b1) {
    __shared__ float xs_t[32 * XS_LD];   // [k][node]
    __shared__ float ws[32 * WS_LD];     // [k][out]
    int t = threadIdx.x;
    int tx = t & 15;        // col group: 6 cols
    int ty = t >> 4;        // node group: 8 nodes
    int nb = blockIdx.x * 128;

    ull acc[4][6];
#pragma unroll
    for (int i = 0; i < 4; i++)
#pragma unroll
        for (int j = 0; j < 6; j++) acc[i][j] = 0ull;

    for (int kc = 0; kc < 4; kc++) {
        __syncthreads();
#pragma unroll
        for (int r = 0; r < 16; r++) {
            int idx = t + 256 * r;
            int n = idx >> 5, k = idx & 31;
            int ng = nb + n;
            float v = (ng < NN) ? x[ng * 128 + kc * 32 + k] : 0.f;
            xs_t[k * XS_LD + n] = v;
        }
#pragma unroll
        for (int r = 0; r < 12; r++) {
            int idx = t + 256 * r;
            int o = idx >> 5, k = idx & 31;
            ws[k * WS_LD + o] = W1[o * 128 + kc * 32 + k];
        }
        __syncthreads();
#pragma unroll
        for (int k = 0; k < 32; k++) {
            ull a2[4];
#pragma unroll
            for (int i = 0; i < 4; i++)
                a2[i] = *reinterpret_cast<const ull*>(&xs_t[k * XS_LD + ty * 8 + 2 * i]);
#pragma unroll
            for (int j = 0; j < 6; j++) {
                ull b2 = pk2(ws[k * WS_LD + tx * 6 + j]);
#pragma unroll
                for (int i = 0; i < 4; i++) ffma2(acc[i][j], a2[i], b2);
            }
        }
    }
    float bb[6];
#pragma unroll
    for (int j = 0; j < 6; j++) bb[j] = b1[tx * 6 + j];
#pragma unroll
    for (int i = 0; i < 4; i++) {
        int n0 = nb + ty * 8 + 2 * i;
#pragma unroll
        for (int j = 0; j < 6; j++) {
            float lo, hi;
            upk2(lo, hi, acc[i][j]);
            lo += bb[j]; hi += bb[j];
            int c = tx * 6 + j;
            if (n0 < NN)     g_xc[n0 * FH + c]       = lo > 0.f ? lo : expm1f(lo);
            if (n0 + 1 < NN) g_xc[(n0 + 1) * FH + c] = hi > 0.f ? hi : expm1f(hi);
        }
    }
}

// ---------------- fused node kernel: projections + y = Wl Y Wr^T ----------------
__global__ void k_node(const float* __restrict__ W_sheaf,
                       const float* __restrict__ W_wt, int layer) {
    int lane = threadIdx.x & 31;
    int warpg = (blockIdx.x * blockDim.x + threadIdx.x) >> 5;
    int nwarps = (gridDim.x * blockDim.x) >> 5;

    const float* ws1 = W_sheaf + layer * 576 + 192;  // row 1 of sheaf learner (D=2)
    float wa0 = ws1[lane], wa1 = ws1[32 + lane], wa2 = ws1[64 + lane];
    float wb0 = ws1[96 + lane], wb1 = ws1[128 + lane], wb2 = ws1[160 + lane];
    const float* ww = W_wt + layer * 192;
    float va0 = ww[lane], va1 = ww[32 + lane], va2 = ww[64 + lane];
    float vb0 = ww[96 + lane], vb1 = ww[128 + lane], vb2 = ww[160 + lane];
    float wl[9];
#pragma unroll
    for (int i = 0; i < 9; i++) wl[i] = g_Wl[layer][i];
    float wrr[32];
#pragma unroll
    for (int h = 0; h < 32; h++) wrr[h] = g_WrT[layer][h * 32 + lane];

    for (int n = warpg; n < NN; n += nwarps) {
        const float* base = g_xc + n * FH;
        float y0 = base[lane], y1 = base[32 + lane], y2 = base[64 + lane];
        float pa = y0 * wa0 + y1 * wa1 + y2 * wa2;
        float pb = y0 * wb0 + y1 * wb1 + y2 * wb2;
        float qa = y0 * va0 + y1 * va1 + y2 * va2;
        float qb = y0 * vb0 + y1 * vb1 + y2 * vb2;
        pa = wsum(pa); pb = wsum(pb); qa = wsum(qa); qb = wsum(qb);
        if (lane == 0) g_n4[n] = make_float4(pa, pb, qa, qb);
        float t0 = wl[0] * y0 + wl[1] * y1 + wl[2] * y2;
        float t1 = wl[3] * y0 + wl[4] * y1 + wl[5] * y2;
        float t2 = wl[6] * y0 + wl[7] * y1 + wl[8] * y2;
        float o0 = 0.f, o1 = 0.f, o2 = 0.f;
#pragma unroll
        for (int h = 0; h < 32; h++) {
            float s0 = __shfl_sync(0xffffffffu, t0, h);
            float s1 = __shfl_sync(0xffffffffu, t1, h);
            float s2 = __shfl_sync(0xffffffffu, t2, h);
            float w = wrr[h];
            o0 += s0 * w; o1 += s1 * w; o2 += s2 * w;
        }
        float* yo = g_y + n * FH;
        yo[lane] = o0; yo[32 + lane] = o1; yo[64 + lane] = o2;
    }
}

// ---------------- fused per-edge scalars + degree + dinv (thread per node) ----------------
__global__ void k_edgedeg() {
    int n = blockIdx.x * blockDim.x + threadIdx.x;
    if (n >= NN) return;
    float4 A = g_n4[n];
    int s = g_off[n], e = g_off[n + 1];
    float deg = 0.f;
    for (int p = s; p < e; p++) {
        int c = g_colc[p];
        float4 B = g_n4[c];
        float w = fsigm(A.z + B.w) * fsigm(B.z + A.w);
        float a = ftanh(A.x + B.y);
        float ar = ftanh(B.x + A.y);
        float i1 = __fdividef(1.f, 1.f + a * a);
        float i2 = __fdividef(1.f, 1.f + ar * ar);
        float ct = (1.f - a * a) * i1, st = 2.f * a * i1;
        float cr = (1.f - ar * ar) * i2, sr = 2.f * ar * i2;
        float4 E;
        float w2 = w * w;
        E.x = w2;
        E.y = ct * cr + st * sr;   // cos(theta_rev - theta)
        E.z = ct * sr - st * cr;   // sin(theta_rev - theta)
        E.w = __int_as_float(c);
        g_e4[p] = E;
        deg += w2;
    }
    g_deg[n] = deg;
    g_dinv[n] = deg > 0.f ? rsqrtf(fmaxf(deg, 1e-30f)) : 0.f;
}

// ---------------- fused Laplacian apply + ELU + residual ----------------
__global__ void k_agg(int layer) {
    int warp = threadIdx.x >> 5, lane = threadIdx.x & 31;
    int n = blockIdx.x * 8 + warp;
    if (n >= NN) return;
    int s = g_off[n], e = g_off[n + 1];
    float dn = g_dinv[n];
    float acc0 = 0.f, acc1 = 0.f, acc2 = 0.f;
    int p = s;
    for (; p + 4 <= e; p += 4) {
        float4 E0 = g_e4[p], E1 = g_e4[p + 1], E2v = g_e4[p + 2], E3 = g_e4[p + 3];
        int c0 = __float_as_int(E0.w), c1 = __float_as_int(E1.w);
        int c2 = __float_as_int(E2v.w), c3 = __float_as_int(E3.w);
        float d0 = g_dinv[c0], d1 = g_dinv[c1], d2 = g_dinv[c2], d3 = g_dinv[c3];
        const float* yp0 = g_y + c0 * FH;
        const float* yp1 = g_y + c1 * FH;
        const float* yp2 = g_y + c2 * FH;
        const float* yp3 = g_y + c3 * FH;
        float a0 = yp0[lane], a1 = yp0[32 + lane], a2 = yp0[64 + lane];
        float b0 = yp1[lane], b1 = yp1[32 + lane], b2 = yp1[64 + lane];
        float e0 = yp2[lane], e1 = yp2[32 + lane], e2 = yp2[64 + lane];
        float f0 = yp3[lane], f1 = yp3[32 + lane], f2 = yp3[64 + lane];
        float cn0 = E0.x * dn * d0, cn1 = E1.x * dn * d1;
        float cn2 = E2v.x * dn * d2, cn3 = E3.x * dn * d3;
        acc0 += cn0 * (E0.y * a0 - E0.z * a1) + cn1 * (E1.y * b0 - E1.z * b1)
              + cn2 * (E2v.y * e0 - E2v.z * e1) + cn3 * (E3.y * f0 - E3.z * f1);
        acc1 += cn0 * (E0.z * a0 + E0.y * a1) + cn1 * (E1.z * b0 + E1.y * b1)
              + cn2 * (E2v.z * e0 + E2v.y * e1) + cn3 * (E3.z * f0 + E3.y * f1);
        acc2 += cn0 * a2 + cn1 * b2 + cn2 * e2 + cn3 * f2;
    }
    for (; p < e; p++) {
        float4 E0 = g_e4[p];
        int c0 = __float_as_int(E0.w);
        float d0 = g_dinv[c0];
        const float* yp0 = g_y + c0 * FH;
        float a0 = yp0[lane], a1 = yp0[32 + lane], a2 = yp0[64 + lane];
        float cn0 = E0.x * dn * d0;
        acc0 += cn0 * (E0.y * a0 - E0.z * a1);
        acc1 += cn0 * (E0.z * a0 + E0.y * a1);
        acc2 += cn0 * a2;
    }
    float diag = (g_deg[n] > 0.f) ? 1.f : 0.f;
    const float* yn = g_y + n * FH;
    float z0 = eluf(diag * yn[lane] - acc0);
    float z1 = eluf(diag * yn[32 + lane] - acc1);
    float z2 = eluf(diag * yn[64 + lane] - acc2);
    float c0 = g_coeff[layer][0], c1 = g_coeff[layer][1], c2 = g_coeff[layer][2];
    float* xn = g_xc + n * FH;
    xn[lane]      = c0 * xn[lane]      - z0;
    xn[32 + lane] = c1 * xn[32 + lane] - z1;
    xn[64 + lane] = c2 * xn[64 + lane] - z2;
}

// ---------------- lin2 ----------------
__global__ void k_lin2(const float* __restrict__ W2, const float* __restrict__ b2,
                       float* __restrict__ out) {
    __shared__ float w2t[96 * 32];
    __shared__ float xs[8][96];
    int t = threadIdx.x;
    for (int i = t; i < 96 * 32; i += 256) {
        int o = i / 96, k = i % 96;
        w2t[k * 32 + o] = W2[i];
    }
    __syncthreads();
    int warp = t >> 5, lane = t & 31;
    float bb = b2[lane];
    int n = blockIdx.x * 8 + warp;
    if (n >= NN) return;
    for (int k = lane; k < 96; k += 32) xs[warp][k] = g_xc[n * FH + k];
    __syncwarp();
    float acc = bb;
#pragma unroll
    for (int k = 0; k < 96; k++) acc += xs[warp][k] * w2t[k * 32 + lane];
    out[n * 32 + lane] = acc;
}

// ---------------- launcher ----------------
extern "C" void kernel_launch(void* const* d_in, const int* in_sizes, int n_in,
                              void* d_out, int out_size) {
    const float* x       = (const float*)d_in[0];
    const int*   ei      = (const int*)d_in[1];
    const float* W1      = (const float*)d_in[2];
    const float* b1      = (const float*)d_in[3];
    const float* W2      = (const float*)d_in[4];
    const float* b2      = (const float*)d_in[5];
    const float* W_left  = (const float*)d_in[6];
    const float* W_right = (const float*)d_in[7];
    const float* eps     = (const float*)d_in[8];
    const float* W_sheaf = (const float*)d_in[9];
    const float* W_wt    = (const float*)d_in[10];
    float* out = (float*)d_out;

    k_zero_cnt<<<NBLK, 256>>>();                     // 0
    k_count<<<(E2 + 255) / 256, 256>>>(ei);          // 1
    k_scanA<<<NBLK, 256>>>();                        // 2
    k_lin1<<<(NN + 127) / 128, 256>>>(x, W1, b1);    // 3  <- profiled launch
    k_scanB_spec<<<3, 256>>>(W_left, W_right, eps);  // 4  (scanB + specnorm fused)
    k_scanC<<<NBLK, 256>>>();                        // 5
    k_scatter<<<(E2 + 255) / 256, 256>>>(ei);        // 6

    for (int layer = 0; layer < 2; layer++) {
        k_node<<<1024, 256>>>(W_sheaf, W_wt, layer);
        k_edgedeg<<<NBLK, 256>>>();
        k_agg<<<(NN + 7) / 8, 256>>>(layer);
    }

    k_lin2<<<(NN + 7) / 8, 256>>>(W2, b2, out);
}

// round 6
// speedup vs baseline: 1.1006x; 1.1006x over previous
#include <cuda_runtime.h>
#include <cuda_bf16.h>
#include <math.h>

#define NN 50000          // nodes
#define E2 400000         // directed edges
#define FH 96             // FD*HID
#define CNTBLK 1563       // ceil(E2/256)
#define LIN1BLK 391       // ceil(NN/128)

typedef unsigned long long ull;

// ---------------- device scratch ----------------
__device__ float g_xc[NN * FH];
__device__ float g_y[NN * FH];
__device__ float4 g_n4[NN];            // {PA, PB, WA, WB}
__device__ float g_deg[NN], g_dinv[NN];
__device__ int   g_cnt[NN];            // zero-initialized at load; self-cleaned each run
__device__ int   g_off[NN + 4];
__device__ int   g_cur[NN + 4];
__device__ int   g_colc[E2];
__device__ float4 g_e4[E2];            // {w2, Tc, Ts, bitcast(col)}
__device__ float g_Wl[2][9];
__device__ float g_WrT[2][1024];       // transposed: [h*32 + c]
__device__ float g_coeff[2][3];

// ---------------- helpers ----------------
__device__ __forceinline__ float eluf(float v) { return v > 0.f ? v : expm1f(v); }
__device__ __forceinline__ float wsum(float v) {
#pragma unroll
    for (int o = 16; o > 0; o >>= 1) v += __shfl_xor_sync(0xffffffffu, v, o);
    return v;
}
__device__ __forceinline__ void ffma2(ull& d, ull a, ull b) {
    asm("fma.rn.f32x2 %0, %1, %2, %0;" : "+l"(d) : "l"(a), "l"(b));
}
__device__ __forceinline__ ull pk2(float v) {
    ull r; asm("mov.b64 %0, {%1, %1};" : "=l"(r) : "f"(v)); return r;
}
__device__ __forceinline__ void upk2(float& lo, float& hi, ull v) {
    asm("mov.b64 {%0, %1}, %2;" : "=f"(lo), "=f"(hi) : "l"(v));
}

// ---------------- lin1 body (FFMA2 register tiling) ----------------
#define XS_LD 134
#define WS_LD 98
__device__ void lin1_body(int lb, const float* __restrict__ x,
                          const float* __restrict__ W1, const float* __restrict__ b1) {
    __shared__ float xs_t[32 * XS_LD];   // [k][node]
    __shared__ float ws[32 * WS_LD];     // [k][out]
    int t = threadIdx.x;
    int tx = t & 15;        // col group: 6 cols
    int ty = t >> 4;        // node group: 8 nodes
    int nb = lb * 128;

    ull acc[4][6];
#pragma unroll
    for (int i = 0; i < 4; i++)
#pragma unroll
        for (int j = 0; j < 6; j++) acc[i][j] = 0ull;

    for (int kc = 0; kc < 4; kc++) {
        __syncthreads();
#pragma unroll
        for (int r = 0; r < 16; r++) {
            int idx = t + 256 * r;
            int n = idx >> 5, k = idx & 31;
            int ng = nb + n;
            float v = (ng < NN) ? x[ng * 128 + kc * 32 + k] : 0.f;
            xs_t[k * XS_LD + n] = v;
        }
#pragma unroll
        for (int r = 0; r < 12; r++) {
            int idx = t + 256 * r;
            int o = idx >> 5, k = idx & 31;
            ws[k * WS_LD + o] = W1[o * 128 + kc * 32 + k];
        }
        __syncthreads();
#pragma unroll
        for (int k = 0; k < 32; k++) {
            ull a2[4];
#pragma unroll
            for (int i = 0; i < 4; i++)
                a2[i] = *reinterpret_cast<const ull*>(&xs_t[k * XS_LD + ty * 8 + 2 * i]);
            const ull* bp = reinterpret_cast<const ull*>(&ws[k * WS_LD + tx * 6]);
            ull p01 = bp[0], p23 = bp[1], p45 = bp[2];
            float f0, f1, f2, f3, f4, f5;
            upk2(f0, f1, p01); upk2(f2, f3, p23); upk2(f4, f5, p45);
            ull B[6];
            B[0] = pk2(f0); B[1] = pk2(f1); B[2] = pk2(f2);
            B[3] = pk2(f3); B[4] = pk2(f4); B[5] = pk2(f5);
#pragma unroll
            for (int j = 0; j < 6; j++)
#pragma unroll
                for (int i = 0; i < 4; i++) ffma2(acc[i][j], a2[i], B[j]);
        }
    }
    float bb[6];
#pragma unroll
    for (int j = 0; j < 6; j++) bb[j] = b1[tx * 6 + j];
#pragma unroll
    for (int i = 0; i < 4; i++) {
        int n0 = nb + ty * 8 + 2 * i;
#pragma unroll
        for (int j = 0; j < 6; j++) {
            float lo, hi;
            upk2(lo, hi, acc[i][j]);
            lo += bb[j]; hi += bb[j];
            int c = tx * 6 + j;
            if (n0 < NN)     g_xc[n0 * FH + c]       = lo > 0.f ? lo : expm1f(lo);
            if (n0 + 1 < NN) g_xc[(n0 + 1) * FH + c] = hi > 0.f ? hi : expm1f(hi);
        }
    }
}

// ---------------- fused: edge count (atomics) + lin1 ----------------
__global__ void __launch_bounds__(256) k_countlin1(const int* __restrict__ ei,
                                                   const float* __restrict__ x,
                                                   const float* __restrict__ W1,
                                                   const float* __restrict__ b1) {
    if (blockIdx.x < CNTBLK) {
        int e = blockIdx.x * 256 + threadIdx.x;
        if (e < E2) atomicAdd(&g_cnt[ei[e]], 1);
        return;
    }
    lin1_body(blockIdx.x - CNTBLK, x, W1, b1);
}

// ---------------- fused: scan (block 0) + spectral norm (blocks 1,2) ----------------
__global__ void k_scanspec(const float* __restrict__ W_left,
                           const float* __restrict__ W_right,
                           const float* __restrict__ eps) {
    if (blockIdx.x == 0) {
        __shared__ int s[32];
        int t = threadIdx.x;        // 1024
        int lane = t & 31, w = t >> 5;
        int base = 0;
        for (int tile = 0; tile < 13; tile++) {
            int i4 = tile * 1024 + t;
            int4 v = make_int4(0, 0, 0, 0);
            if (i4 < NN / 4) v = ((const int4*)g_cnt)[i4];
            int local = v.x + v.y + v.z + v.w;
            // warp inclusive scan
            int vi = local;
#pragma unroll
            for (int o = 1; o < 32; o <<= 1) {
                int xq = __shfl_up_sync(0xffffffffu, vi, o);
                if (lane >= o) vi += xq;
            }
            if (lane == 31) s[w] = vi;
            __syncthreads();
            if (w == 0) {
                int a = s[lane];
#pragma unroll
                for (int o = 1; o < 32; o <<= 1) {
                    int xq = __shfl_up_sync(0xffffffffu, a, o);
                    if (lane >= o) a += xq;
                }
                s[lane] = a;
            }
            __syncthreads();
            int wbase = (w > 0) ? s[w - 1] : 0;
            int excl = wbase + vi - local;
            int total = s[31];
            if (i4 < NN / 4) {
                int4 o4;
                o4.x = base + excl;
                o4.y = o4.x + v.x;
                o4.z = o4.y + v.y;
                o4.w = o4.z + v.z;
                ((int4*)g_off)[i4] = o4;
                ((int4*)g_cur)[i4] = o4;
                ((int4*)g_cnt)[i4] = make_int4(0, 0, 0, 0);   // self-clean for next run
            }
            base += total;
            __syncthreads();
        }
        if (t == 0) g_off[NN] = base;
        return;
    }
    // ---- spectral norm (one warp per block) ----
    int layer = blockIdx.x - 1;
    int lane = threadIdx.x;
    if (lane >= 32) return;
    __shared__ float ws[32 * 33];
    for (int i = lane; i < 1024; i += 32) {
        int r = i >> 5, c = i & 31;
        ws[r * 33 + c] = W_right[layer * 1024 + i];
    }
    __syncwarp();
    float u = 1.f / sqrtf(32.f);
    for (int it = 0; it < 20; it++) {
        float v = 0.f;
#pragma unroll 8
        for (int i = 0; i < 32; i++) v += ws[i * 33 + lane] * __shfl_sync(0xffffffffu, u, i);
        float un = 0.f;
#pragma unroll 8
        for (int j = 0; j < 32; j++) un += ws[lane * 33 + j] * __shfl_sync(0xffffffffu, v, j);
        float nu = sqrtf(wsum(un * un));
        u = un / (nu + 1e-12f);
    }
    float v = 0.f;
    for (int i = 0; i < 32; i++) v += ws[i * 33 + lane] * __shfl_sync(0xffffffffu, u, i);
    float nv = sqrtf(wsum(v * v));
    v = v / (nv + 1e-12f);
    float wv = 0.f;
    for (int j = 0; j < 32; j++) wv += ws[lane * 33 + j] * __shfl_sync(0xffffffffu, v, j);
    float sigma = wsum(u * wv);
    float inv = 1.f / sigma;
    for (int i = lane; i < 1024; i += 32) {
        int c = i >> 5, h = i & 31;
        g_WrT[layer][h * 32 + c] = W_right[layer * 1024 + i] * inv;
    }
    if (lane == 0) {
        float W[9];
        for (int i = 0; i < 9; i++) W[i] = W_left[layer * 9 + i];
        float uu[3] = {0.5773502691896258f, 0.5773502691896258f, 0.5773502691896258f};
        float vv[3];
        for (int it = 0; it < 20; it++) {
            vv[0] = vv[1] = vv[2] = 0.f;
            for (int i = 0; i < 3; i++)
                for (int j = 0; j < 3; j++) vv[j] += W[i * 3 + j] * uu[i];
            float n2 = sqrtf(vv[0] * vv[0] + vv[1] * vv[1] + vv[2] * vv[2]) + 1e-12f;
            for (int j = 0; j < 3; j++) vv[j] /= n2;
            float u2[3] = {0.f, 0.f, 0.f};
            for (int i = 0; i < 3; i++)
                for (int j = 0; j < 3; j++) u2[i] += W[i * 3 + j] * vv[j];
            float n3 = sqrtf(u2[0] * u2[0] + u2[1] * u2[1] + u2[2] * u2[2]) + 1e-12f;
            for (int i = 0; i < 3; i++) uu[i] = u2[i] / n3;
        }
        vv[0] = vv[1] = vv[2] = 0.f;
        for (int i = 0; i < 3; i++)
            for (int j = 0; j < 3; j++) vv[j] += W[i * 3 + j] * uu[i];
        float n2 = sqrtf(vv[0] * vv[0] + vv[1] * vv[1] + vv[2] * vv[2]) + 1e-12f;
        for (int j = 0; j < 3; j++) vv[j] /= n2;
        float sig = 0.f;
        for (int i = 0; i < 3; i++) {
            float tq = 0.f;
            for (int j = 0; j < 3; j++) tq += W[i * 3 + j] * vv[j];
            sig += uu[i] * tq;
        }
        float is = 1.f / sig;
        for (int i = 0; i < 9; i++) g_Wl[layer][i] = W[i] * is;
        for (int f = 0; f < 3; f++) g_coeff[layer][f] = 1.f + tanhf(eps[layer * 3 + f]);
    }
}

// ---------------- node body: projections + y = Wl Y Wr^T ----------------
__device__ void node_body(const float* __restrict__ W_sheaf, const float* __restrict__ W_wt,
                          int layer, int vbid, int nblocks) {
    int lane = threadIdx.x & 31;
    int warpg = (vbid * 256 + threadIdx.x) >> 5;
    int nwarps = nblocks * 8;

    const float* ws1 = W_sheaf + layer * 576 + 192;  // row 1 of sheaf learner (D=2)
    float wa0 = ws1[lane], wa1 = ws1[32 + lane], wa2 = ws1[64 + lane];
    float wb0 = ws1[96 + lane], wb1 = ws1[128 + lane], wb2 = ws1[160 + lane];
    const float* ww = W_wt + layer * 192;
    float va0 = ww[lane], va1 = ww[32 + lane], va2 = ww[64 + lane];
    float vb0 = ww[96 + lane], vb1 = ww[128 + lane], vb2 = ww[160 + lane];
    float wl[9];
#pragma unroll
    for (int i = 0; i < 9; i++) wl[i] = g_Wl[layer][i];
    float wrr[32];
#pragma unroll
    for (int h = 0; h < 32; h++) wrr[h] = g_WrT[layer][h * 32 + lane];

    for (int n = warpg; n < NN; n += nwarps) {
        const float* base = g_xc + n * FH;
        float y0 = base[lane], y1 = base[32 + lane], y2 = base[64 + lane];
        float pa = y0 * wa0 + y1 * wa1 + y2 * wa2;
        float pb = y0 * wb0 + y1 * wb1 + y2 * wb2;
        float qa = y0 * va0 + y1 * va1 + y2 * va2;
        float qb = y0 * vb0 + y1 * vb1 + y2 * vb2;
        pa = wsum(pa); pb = wsum(pb); qa = wsum(qa); qb = wsum(qb);
        if (lane == 0) g_n4[n] = make_float4(pa, pb, qa, qb);
        float t0 = wl[0] * y0 + wl[1] * y1 + wl[2] * y2;
        float t1 = wl[3] * y0 + wl[4] * y1 + wl[5] * y2;
        float t2 = wl[6] * y0 + wl[7] * y1 + wl[8] * y2;
        float o0 = 0.f, o1 = 0.f, o2 = 0.f;
#pragma unroll
        for (int h = 0; h < 32; h++) {
            float s0 = __shfl_sync(0xffffffffu, t0, h);
            float s1 = __shfl_sync(0xffffffffu, t1, h);
            float s2 = __shfl_sync(0xffffffffu, t2, h);
            float w = wrr[h];
            o0 += s0 * w; o1 += s1 * w; o2 += s2 * w;
        }
        float* yo = g_y + n * FH;
        yo[lane] = o0; yo[32 + lane] = o1; yo[64 + lane] = o2;
    }
}

// ---------------- fused: scatter + node(layer 0) ----------------
__global__ void k_scatnode(const int* __restrict__ ei,
                           const float* __restrict__ W_sheaf,
                           const float* __restrict__ W_wt) {
    if (blockIdx.x < CNTBLK) {
        int e = blockIdx.x * 256 + threadIdx.x;
        if (e < E2) {
            int r = ei[e];
            int p = atomicAdd(&g_cur[r], 1);
            g_colc[p] = ei[E2 + e];
        }
        return;
    }
    node_body(W_sheaf, W_wt, 0, blockIdx.x - CNTBLK, 1024);
}

// ---------------- node standalone (layer 1) ----------------
__global__ void k_node(const float* __restrict__ W_sheaf,
                       const float* __restrict__ W_wt, int layer) {
    node_body(W_sheaf, W_wt, layer, blockIdx.x, gridDim.x);
}

// ---------------- per-edge scalars + degree + dinv (thread per node) ----------------
__global__ void k_edgedeg() {
    int n = blockIdx.x * blockDim.x + threadIdx.x;
    if (n >= NN) return;
    float4 A = g_n4[n];
    int s = g_off[n], e = g_off[n + 1];
    float deg = 0.f;
    for (int p = s; p < e; p++) {
        int c = g_colc[p];
        float4 B = g_n4[c];
        // w = sigma(A.z+B.w)*sigma(B.z+A.w); w2 = w*w
        float ew1 = __expf(-(A.z + B.w));
        float ew2 = __expf(-(B.z + A.w));
        float w = __frcp_rn((1.f + ew1) * (1.f + ew2));
        float w2 = w * w;
        // rotation: ct = sech(2p), st = tanh(2p), p = tanh-input
        float p1 = fminf(fmaxf(A.x + B.y, -10.f), 10.f);
        float p2 = fminf(fmaxf(B.x + A.y, -10.f), 10.f);
        float t1 = __expf(2.f * p1), t2 = __expf(2.f * p2);
        float q1 = t1 * t1, q2 = t2 * t2;
        float d1 = __frcp_rn(q1 + 1.f), d2 = __frcp_rn(q2 + 1.f);
        float st = (q1 - 1.f) * d1, ct = 2.f * t1 * d1;
        float sr = (q2 - 1.f) * d2, cr = 2.f * t2 * d2;
        float4 E;
        E.x = w2;
        E.y = ct * cr + st * sr;   // cos(theta_rev - theta)
        E.z = ct * sr - st * cr;   // sin(theta_rev - theta)
        E.w = __int_as_float(c);
        g_e4[p] = E;
        deg += w2;
    }
    g_deg[n] = deg;
    g_dinv[n] = deg > 0.f ? rsqrtf(fmaxf(deg, 1e-30f)) : 0.f;
}

// ---------------- agg core: returns updated x values for this node ----------------
__device__ void agg_core(int n, int lane, int layer, float& x0o, float& x1o, float& x2o) {
    int s = g_off[n], e = g_off[n + 1];
    float dn = g_dinv[n];
    float acc0 = 0.f, acc1 = 0.f, acc2 = 0.f;
    int p = s;
    for (; p + 4 <= e; p += 4) {
        float4 E0 = g_e4[p], E1 = g_e4[p + 1], E2v = g_e4[p + 2], E3 = g_e4[p + 3];
        int c0 = __float_as_int(E0.w), c1 = __float_as_int(E1.w);
        int c2 = __float_as_int(E2v.w), c3 = __float_as_int(E3.w);
        float d0 = g_dinv[c0], d1 = g_dinv[c1], d2 = g_dinv[c2], d3 = g_dinv[c3];
        const float* yp0 = g_y + c0 * FH;
        const float* yp1 = g_y + c1 * FH;
        const float* yp2 = g_y + c2 * FH;
        const float* yp3 = g_y + c3 * FH;
        float a0 = yp0[lane], a1 = yp0[32 + lane], a2 = yp0[64 + lane];
        float b0 = yp1[lane], b1 = yp1[32 + lane], b2 = yp1[64 + lane];
        float e0 = yp2[lane], e1 = yp2[32 + lane], e2 = yp2[64 + lane];
        float f0 = yp3[lane], f1 = yp3[32 + lane], f2 = yp3[64 + lane];
        float cn0 = E0.x * dn * d0, cn1 = E1.x * dn * d1;
        float cn2 = E2v.x * dn * d2, cn3 = E3.x * dn * d3;
        acc0 += cn0 * (E0.y * a0 - E0.z * a1) + cn1 * (E1.y * b0 - E1.z * b1)
              + cn2 * (E2v.y * e0 - E2v.z * e1) + cn3 * (E3.y * f0 - E3.z * f1);
        acc1 += cn0 * (E0.z * a0 + E0.y * a1) + cn1 * (E1.z * b0 + E1.y * b1)
              + cn2 * (E2v.z * e0 + E2v.y * e1) + cn3 * (E3.z * f0 + E3.y * f1);
        acc2 += cn0 * a2 + cn1 * b2 + cn2 * e2 + cn3 * f2;
    }
    for (; p < e; p++) {
        float4 E0 = g_e4[p];
        int c0 = __float_as_int(E0.w);
        float d0 = g_dinv[c0];
        const float* yp0 = g_y + c0 * FH;
        float a0 = yp0[lane], a1 = yp0[32 + lane], a2 = yp0[64 + lane];
        float cn0 = E0.x * dn * d0;
        acc0 += cn0 * (E0.y * a0 - E0.z * a1);
        acc1 += cn0 * (E0.z * a0 + E0.y * a1);
        acc2 += cn0 * a2;
    }
    float diag = (g_deg[n] > 0.f) ? 1.f : 0.f;
    const float* yn = g_y + n * FH;
    float z0 = eluf(diag * yn[lane] - acc0);
    float z1 = eluf(diag * yn[32 + lane] - acc1);
    float z2 = eluf(diag * yn[64 + lane] - acc2);
    float c0 = g_coeff[layer][0], c1 = g_coeff[layer][1], c2 = g_coeff[layer][2];
    const float* xn = g_xc + n * FH;
    x0o = c0 * xn[lane]      - z0;
    x1o = c1 * xn[32 + lane] - z1;
    x2o = c2 * xn[64 + lane] - z2;
}

// ---------------- layer 0: agg -> write xc ----------------
__global__ void k_agg(int layer) {
    int warp = threadIdx.x >> 5, lane = threadIdx.x & 31;
    int n = blockIdx.x * 8 + warp;
    float x0, x1, x2;
    agg_core(n, lane, layer, x0, x1, x2);
    float* xn = g_xc + n * FH;
    xn[lane] = x0; xn[32 + lane] = x1; xn[64 + lane] = x2;
}

// ---------------- layer 1: agg fused with lin2 -> write out ----------------
__global__ void k_agg_lin2(const float* __restrict__ W2, const float* __restrict__ b2,
                           float* __restrict__ out) {
    __shared__ float w2t[96 * 32];   // [k][o]
    __shared__ float sx[8][96];
    int t = threadIdx.x;
    for (int i = t; i < 96 * 32; i += 256) {
        int o = i / 96, k = i % 96;
        w2t[k * 32 + o] = W2[i];
    }
    __syncthreads();
    int warp = t >> 5, lane = t & 31;
    int n = blockIdx.x * 8 + warp;
    float x0, x1, x2;
    agg_core(n, lane, 1, x0, x1, x2);
    sx[warp][lane] = x0; sx[warp][32 + lane] = x1; sx[warp][64 + lane] = x2;
    __syncwarp();
    float acc = b2[lane];
#pragma unroll
    for (int k = 0; k < 96; k++) acc += sx[warp][k] * w2t[k * 32 + lane];
    out[n * 32 + lane] = acc;
}

// ---------------- launcher ----------------
extern "C" void kernel_launch(void* const* d_in, const int* in_sizes, int n_in,
                              void* d_out, int out_size) {
    const float* x       = (const float*)d_in[0];
    const int*   ei      = (const int*)d_in[1];
    const float* W1      = (const float*)d_in[2];
    const float* b1      = (const float*)d_in[3];
    const float* W2      = (const float*)d_in[4];
    const float* b2      = (const float*)d_in[5];
    const float* W_left  = (const float*)d_in[6];
    const float* W_right = (const float*)d_in[7];
    const float* eps     = (const float*)d_in[8];
    const float* W_sheaf = (const float*)d_in[9];
    const float* W_wt    = (const float*)d_in[10];
    float* out = (float*)d_out;

    k_countlin1<<<CNTBLK + LIN1BLK, 256>>>(ei, x, W1, b1);          // 0
    k_scanspec<<<3, 1024>>>(W_left, W_right, eps);                  // 1
    k_scatnode<<<CNTBLK + 1024, 256>>>(ei, W_sheaf, W_wt);          // 2
    k_edgedeg<<<(NN + 255) / 256, 256>>>();                         // 3 <- profiled
    k_agg<<<NN / 8, 256>>>(0);                                      // 4
    k_node<<<1024, 256>>>(W_sheaf, W_wt, 1);                        // 5
    k_edgedeg<<<(NN + 255) / 256, 256>>>();                         // 6
    k_agg_lin2<<<NN / 8, 256>>>(W2, b2, out);                       // 7
}